// round 12
// baseline (speedup 1.0000x reference)
#include <cuda_runtime.h>
#include <cuda_fp16.h>
#include <cstdint>

// out[m,o] = sum_d FWHT(x)[m,d] * W[o,d] / sqrt(D) + b[o]
// Hadamard symmetric => FWHT(x) @ W^T == x @ (FWHT_rows(W))^T.
// fp16 single-pass HMMA GEMM w/ fp32 acc.
// R12 = R11 + next-chunk cp.async distributed 3-per-ks-step inside half-0
// compute (kills the mid-loop LSU burst), converter uses MLP=4 loads.

#define D_DIM 2048
#define M_ROWS 16384
#define KDIM 2048
#define NDIM 2048

#define BM 256
#define BN 128
#define BKH 64                       // layout sub-chunk
#define NCH (KDIM / (2 * BKH))       // 16 double-chunks
#define TILE_A_B (BM * 128)          // 32 KB per k-half
#define TILE_B_B (BN * 128)          // 16 KB per k-half
#define HALF_B (TILE_A_B + TILE_B_B) // 48 KB
#define STAGE_B (2 * HALF_B)         // 96 KB (BK=128)
#define SMEM_TOTAL (2 * STAGE_B)     // 192 KB, 1 CTA/SM

// ---- device-global scratch ----
__device__ __half g_W_h[(size_t)NDIM * KDIM];     // 8 MB
__device__ __half g_x_h[(size_t)M_ROWS * KDIM];   // 64 MB

// ====================== PTX helpers ======================
__device__ __forceinline__ uint32_t smem_u32(const void* p) {
    uint32_t a;
    asm("{ .reg .u64 t; cvta.to.shared.u64 t, %1; cvt.u32.u64 %0, t; }" : "=r"(a) : "l"(p));
    return a;
}
#define CP16(dst, src) \
    asm volatile("cp.async.cg.shared.global [%0], [%1], 16;" :: "r"(dst), "l"(src))
#define CP_COMMIT() asm volatile("cp.async.commit_group;" ::: "memory")
#define CP_WAIT0()  asm volatile("cp.async.wait_group 0;" ::: "memory")

#define LDSM4(r0, r1, r2, r3, addr) \
    asm volatile("ldmatrix.sync.aligned.m8n8.x4.shared.b16 {%0,%1,%2,%3}, [%4];" \
                 : "=r"(r0), "=r"(r1), "=r"(r2), "=r"(r3) : "r"(addr))

__device__ __forceinline__ void mma16816(float* c, const uint32_t* a,
                                         uint32_t b0, uint32_t b1) {
    asm volatile(
        "mma.sync.aligned.m16n8k16.row.col.f32.f16.f16.f32 "
        "{%0,%1,%2,%3}, {%4,%5,%6,%7}, {%8,%9}, {%0,%1,%2,%3};"
        : "+f"(c[0]), "+f"(c[1]), "+f"(c[2]), "+f"(c[3])
        : "r"(a[0]), "r"(a[1]), "r"(a[2]), "r"(a[3]), "r"(b0), "r"(b1));
}

// ============ Kernel 1 (merged preprocessing) ============
// blocks [0, 1024):  FWHT two rows of W -> fp16 (shared syncs)
// blocks [1024, ..): convert 4 float4-chunks of x -> fp16 (MLP=4)
#define FWHT_BLKS (D_DIM / 2)
#define CONV_F4_PER_THREAD 4
__global__ __launch_bounds__(256) void preprocess(const float* __restrict__ W,
                                                  const float* __restrict__ x) {
    __shared__ float s[2 * D_DIM];
    const int tid = threadIdx.x;
    if (blockIdx.x < FWHT_BLKS) {
        const float* rows = W + (size_t)blockIdx.x * 2 * D_DIM;
        for (int i = tid; i < 2 * D_DIM; i += 256) s[i] = rows[i];
        __syncthreads();
        #pragma unroll
        for (int lg = 0; lg < 11; lg++) {
            int h = 1 << lg;
            #pragma unroll
            for (int rr = 0; rr < 2; rr++) {
                float* sr = s + rr * D_DIM;
                #pragma unroll
                for (int q = 0; q < (D_DIM / 2) / 256; q++) {
                    int p = tid + q * 256;
                    int i = ((p >> lg) << (lg + 1)) | (p & (h - 1));
                    float a = sr[i], c = sr[i + h];
                    sr[i] = a + c;
                    sr[i + h] = a - c;
                }
            }
            __syncthreads();
        }
        const float scale = 0.02209708691207961f;  // 1/sqrt(2048)
        size_t base = (size_t)blockIdx.x * 2 * D_DIM;
        for (int i = tid; i < 2 * D_DIM; i += 256)
            g_W_h[base + i] = __float2half_rn(s[i] * scale);
    } else {
        size_t b = (size_t)(blockIdx.x - FWHT_BLKS) * (256 * CONV_F4_PER_THREAD) + tid;
        float4 v[CONV_F4_PER_THREAD];
        #pragma unroll
        for (int u = 0; u < CONV_F4_PER_THREAD; u++)        // front-batched MLP
            v[u] = ((const float4*)x)[b + (size_t)u * 256];
        #pragma unroll
        for (int u = 0; u < CONV_F4_PER_THREAD; u++) {
            size_t i = b + (size_t)u * 256;
            ((__half2*)g_x_h)[2 * i]     = __floats2half2_rn(v[u].x, v[u].y);
            ((__half2*)g_x_h)[2 * i + 1] = __floats2half2_rn(v[u].z, v[u].w);
        }
    }
}

// ====================== Kernel 2: fp16 HMMA GEMM + bias ======================
// 16 warps: wm = wid&3 (4 x 64 rows), wn = wid>>2 (4 x 32 cols).
// Warp tile 64x32: per k16-step A 4 LDSM4 + B 2 LDSM4, 16 MMAs.
// Next-chunk copies: 3 cp.async per ks-step of half-0 (12 total), commit
// between halves (same pipeline safety as R11).

__global__ __launch_bounds__(512, 1)
void had_gemm_f16(const float* __restrict__ bias, float* __restrict__ C) {
    extern __shared__ __align__(1024) char smem[];
    const uint32_t sm0 = smem_u32(smem);

    const int tid  = threadIdx.x;
    const int lane = tid & 31;
    const int wid  = tid >> 5;
    const int wm   = wid & 3;
    const int wn   = wid >> 2;

    const int bm = blockIdx.y * BM;
    const int bn = blockIdx.x * BN;

    // ---- cp.async loader mapping ----
    const int lr = tid >> 3;      // 0..63
    const int lc = tid & 7;       // 16B chunk
    const uint32_t swchunk = (uint32_t)((lc ^ (lr & 7)) << 4);

    const __half* srcA = g_x_h + (size_t)(bm + lr) * KDIM + lc * 8;
    const __half* srcB = g_W_h + (size_t)(bn + lr) * KDIM + lc * 8;

    float acc[4][4][4];
    #pragma unroll
    for (int i = 0; i < 4; i++)
        #pragma unroll
        for (int j = 0; j < 4; j++)
            #pragma unroll
            for (int q = 0; q < 4; q++) acc[i][j][q] = 0.f;

    // ---- ldmatrix per-thread address components (inline recompute) ----
    const int raBase = wm * 64 + (lane & 15);                      // + tm*16
    const int cA     = lane >> 4;
    const int rbBase = wn * 32 + (lane & 7) + ((lane >> 4) << 3);  // + g*16
    const int cB     = (lane >> 3) & 1;

    // one copy of the 12-copy next-chunk set; idx in [0,12)
    // idx/6 = k-half, idx%6: 0..3 -> A row-sweep, 4..5 -> B row-sweep
    auto issue_one = [&](uint32_t nsb, size_t ntb, int idx) {
        const int h01 = idx / 6;
        const int j = idx % 6;
        const uint32_t hb = nsb + h01 * HALF_B;
        const size_t ko = ntb + (size_t)h01 * BKH;
        if (j < 4) {
            uint32_t roff = (uint32_t)(lr + 64 * j) * 128 + swchunk;
            CP16(hb + roff, srcA + ko + (size_t)(64 * j) * KDIM);
        } else {
            const int i = j - 4;
            uint32_t roff = (uint32_t)(lr + 64 * i) * 128 + swchunk;
            CP16(hb + TILE_A_B + roff, srcB + ko + (size_t)(64 * i) * KDIM);
        }
    };

    // one ks-step of LDSM + MMA from k-half base aT
    auto step = [&](uint32_t aT, int ks) {
        const uint32_t bT = aT + TILE_A_B;
        uint32_t ah[4][4], bh[2][4];
        #pragma unroll
        for (int tm = 0; tm < 4; tm++) {
            const int r = raBase + tm * 16;
            const uint32_t off = (uint32_t)r * 128 +
                                 (uint32_t)(((2 * ks + cA) ^ (r & 7)) << 4);
            LDSM4(ah[tm][0], ah[tm][1], ah[tm][2], ah[tm][3], aT + off);
        }
        #pragma unroll
        for (int g = 0; g < 2; g++) {
            const int r = rbBase + g * 16;
            const uint32_t off = (uint32_t)r * 128 +
                                 (uint32_t)(((2 * ks + cB) ^ (r & 7)) << 4);
            LDSM4(bh[g][0], bh[g][1], bh[g][2], bh[g][3], bT + off);
        }
        #pragma unroll
        for (int tm = 0; tm < 4; tm++) {
            #pragma unroll
            for (int g = 0; g < 2; g++) {
                #pragma unroll
                for (int h = 0; h < 2; h++) {
                    mma16816(acc[tm][g * 2 + h], ah[tm],
                             bh[g][2 * h], bh[g][2 * h + 1]);
                }
            }
        }
    };

    // prologue: chunk 0 -> stage 0
    {
        const uint32_t nsb = sm0;
        #pragma unroll
        for (int idx = 0; idx < 12; idx++) issue_one(nsb, 0, idx);
        CP_COMMIT();
    }

    for (int t = 0; t < NCH; t++) {
        CP_WAIT0();            // chunk t fully in smem
        __syncthreads();

        const uint32_t sb  = sm0 + (t & 1) * STAGE_B;
        const uint32_t nsb = sm0 + ((t + 1) & 1) * STAGE_B;
        const size_t ntb = (size_t)(t + 1) * (2 * BKH);
        const bool di = (t + 1 < NCH);

        // half 0: compute with 3 distributed next-chunk copies per ks
        #pragma unroll
        for (int ks = 0; ks < 4; ks++) {
            step(sb, ks);
            if (di) {
                issue_one(nsb, ntb, 3 * ks + 0);
                issue_one(nsb, ntb, 3 * ks + 1);
                issue_one(nsb, ntb, 3 * ks + 2);
            }
        }
        CP_COMMIT();

        // half 1: pure compute
        #pragma unroll
        for (int ks = 0; ks < 4; ks++) step(sb + HALF_B, ks);
    }

    // ---- epilogue: add bias, store ----
    float2 bv[4];
    #pragma unroll
    for (int j = 0; j < 4; j++) {
        const int n = bn + wn * 32 + j * 8 + 2 * (lane & 3);
        bv[j] = *(const float2*)(bias + n);
    }
    #pragma unroll
    for (int tm = 0; tm < 4; tm++) {
        const int r0 = bm + wm * 64 + tm * 16 + (lane >> 2);
        #pragma unroll
        for (int j = 0; j < 4; j++) {
            const int n = bn + wn * 32 + j * 8 + 2 * (lane & 3);
            float2 o0, o1;
            o0.x = acc[tm][j][0] + bv[j].x;
            o0.y = acc[tm][j][1] + bv[j].y;
            o1.x = acc[tm][j][2] + bv[j].x;
            o1.y = acc[tm][j][3] + bv[j].y;
            *(float2*)(C + (size_t)r0 * NDIM + n)       = o0;
            *(float2*)(C + (size_t)(r0 + 8) * NDIM + n) = o1;
        }
    }
}

// ====================== host launch ======================
extern "C" void kernel_launch(void* const* d_in, const int* in_sizes, int n_in,
                              void* d_out, int out_size) {
    const float* x    = (const float*)d_in[0];   // (4,4096,2048) fp32
    const float* W    = (const float*)d_in[1];   // (2048,2048) fp32
    const float* bias = (const float*)d_in[2];   // (2048,) fp32
    float* out        = (float*)d_out;

    static bool attr_set = false;
    if (!attr_set) {
        cudaFuncSetAttribute(had_gemm_f16, cudaFuncAttributeMaxDynamicSharedMemorySize,
                             SMEM_TOTAL);
        attr_set = true;
    }

    const int conv_blocks = (M_ROWS * KDIM / 4) / (256 * CONV_F4_PER_THREAD);
    preprocess<<<FWHT_BLKS + conv_blocks, 256>>>(W, x);

    dim3 grid(NDIM / BN, M_ROWS / BM);   // bn fastest -> A-stripe L2 reuse
    had_gemm_f16<<<grid, 512, SMEM_TOTAL>>>(bias, out);
}

// round 13
// speedup vs baseline: 1.0402x; 1.0402x over previous
#include <cuda_runtime.h>
#include <cuda_fp16.h>
#include <cstdint>

// out[m,o] = sum_d FWHT(x)[m,d] * W[o,d] / sqrt(D) + b[o]
// Hadamard symmetric => FWHT(x) @ W^T == x @ (FWHT_rows(W))^T.
// fp16 single-pass HMMA GEMM w/ fp32 acc.
// R13: 128x128 CTA tile, 8 warps (2m x 4n, 64x32 each), BK=64, 3-stage
// distance-2 pipeline, 96KB smem, 2 CTAs/SM -> cross-CTA overlap covers
// barrier drain + prologue + epilogue idle (R11's residual 23%).
// MMA block kept pure; copies at ONE mid-chunk point (R9/R12 lesson).

#define D_DIM 2048
#define M_ROWS 16384
#define KDIM 2048
#define NDIM 2048

#define BM 128
#define BN 128
#define BK 64
#define NCH (KDIM / BK)              // 32 chunks
#define STAGES 3
#define TILE_A_B (BM * 128)          // 16 KB
#define TILE_B_B (BN * 128)          // 16 KB
#define STAGE_B (TILE_A_B + TILE_B_B)    // 32 KB
#define SMEM_TOTAL (STAGES * STAGE_B)    // 96 KB -> 2 CTAs/SM

// ---- device-global scratch ----
__device__ __half g_W_h[(size_t)NDIM * KDIM];     // 8 MB
__device__ __half g_x_h[(size_t)M_ROWS * KDIM];   // 64 MB

// ====================== PTX helpers ======================
__device__ __forceinline__ uint32_t smem_u32(const void* p) {
    uint32_t a;
    asm("{ .reg .u64 t; cvta.to.shared.u64 t, %1; cvt.u32.u64 %0, t; }" : "=r"(a) : "l"(p));
    return a;
}
#define CP16(dst, src) \
    asm volatile("cp.async.cg.shared.global [%0], [%1], 16;" :: "r"(dst), "l"(src))
#define CP_COMMIT() asm volatile("cp.async.commit_group;" ::: "memory")
#define CP_WAIT1()  asm volatile("cp.async.wait_group 1;" ::: "memory")

#define LDSM4(r0, r1, r2, r3, addr) \
    asm volatile("ldmatrix.sync.aligned.m8n8.x4.shared.b16 {%0,%1,%2,%3}, [%4];" \
                 : "=r"(r0), "=r"(r1), "=r"(r2), "=r"(r3) : "r"(addr))

__device__ __forceinline__ void mma16816(float* c, const uint32_t* a,
                                         uint32_t b0, uint32_t b1) {
    asm volatile(
        "mma.sync.aligned.m16n8k16.row.col.f32.f16.f16.f32 "
        "{%0,%1,%2,%3}, {%4,%5,%6,%7}, {%8,%9}, {%0,%1,%2,%3};"
        : "+f"(c[0]), "+f"(c[1]), "+f"(c[2]), "+f"(c[3])
        : "r"(a[0]), "r"(a[1]), "r"(a[2]), "r"(a[3]), "r"(b0), "r"(b1));
}

// ============ Kernel 1 (merged preprocessing) ============
// blocks [0, 1024):  FWHT two rows of W -> fp16 (shared syncs)
// blocks [1024, ..): convert 4 float4-chunks of x -> fp16 (MLP=4)
#define FWHT_BLKS (D_DIM / 2)
#define CONV_F4_PER_THREAD 4
__global__ __launch_bounds__(256) void preprocess(const float* __restrict__ W,
                                                  const float* __restrict__ x) {
    __shared__ float s[2 * D_DIM];
    const int tid = threadIdx.x;
    if (blockIdx.x < FWHT_BLKS) {
        const float* rows = W + (size_t)blockIdx.x * 2 * D_DIM;
        for (int i = tid; i < 2 * D_DIM; i += 256) s[i] = rows[i];
        __syncthreads();
        #pragma unroll
        for (int lg = 0; lg < 11; lg++) {
            int h = 1 << lg;
            #pragma unroll
            for (int rr = 0; rr < 2; rr++) {
                float* sr = s + rr * D_DIM;
                #pragma unroll
                for (int q = 0; q < (D_DIM / 2) / 256; q++) {
                    int p = tid + q * 256;
                    int i = ((p >> lg) << (lg + 1)) | (p & (h - 1));
                    float a = sr[i], c = sr[i + h];
                    sr[i] = a + c;
                    sr[i + h] = a - c;
                }
            }
            __syncthreads();
        }
        const float scale = 0.02209708691207961f;  // 1/sqrt(2048)
        size_t base = (size_t)blockIdx.x * 2 * D_DIM;
        for (int i = tid; i < 2 * D_DIM; i += 256)
            g_W_h[base + i] = __float2half_rn(s[i] * scale);
    } else {
        size_t b = (size_t)(blockIdx.x - FWHT_BLKS) * (256 * CONV_F4_PER_THREAD) + tid;
        float4 v[CONV_F4_PER_THREAD];
        #pragma unroll
        for (int u = 0; u < CONV_F4_PER_THREAD; u++)
            v[u] = ((const float4*)x)[b + (size_t)u * 256];
        #pragma unroll
        for (int u = 0; u < CONV_F4_PER_THREAD; u++) {
            size_t i = b + (size_t)u * 256;
            ((__half2*)g_x_h)[2 * i]     = __floats2half2_rn(v[u].x, v[u].y);
            ((__half2*)g_x_h)[2 * i + 1] = __floats2half2_rn(v[u].z, v[u].w);
        }
    }
}

// ====================== Kernel 2: fp16 HMMA GEMM + bias ======================
// 8 warps: wm = wid&1 (2 x 64 rows), wn = wid>>1 (4 x 32 cols).
// Warp tile 64x32: per k16-step A 4 LDSM4 + B 2 LDSM4, 16 MMAs.

__global__ __launch_bounds__(256, 2)
void had_gemm_f16(const float* __restrict__ bias, float* __restrict__ C) {
    extern __shared__ __align__(1024) char smem[];
    const uint32_t sm0 = smem_u32(smem);

    const int tid  = threadIdx.x;
    const int lane = tid & 31;
    const int wid  = tid >> 5;
    const int wm   = wid & 1;
    const int wn   = wid >> 1;

    const int bm = blockIdx.y * BM;
    const int bn = blockIdx.x * BN;

    // ---- cp.async loader mapping: 256 threads, row lr (+32*i), chunk lc ----
    const int lr = tid >> 3;      // 0..31
    const int lc = tid & 7;       // 16B chunk
    const uint32_t swchunk = (uint32_t)((lc ^ (lr & 7)) << 4);

    const __half* srcA = g_x_h + (size_t)(bm + lr) * KDIM + lc * 8;
    const __half* srcB = g_W_h + (size_t)(bn + lr) * KDIM + lc * 8;

    float acc[4][4][4];
    #pragma unroll
    for (int i = 0; i < 4; i++)
        #pragma unroll
        for (int j = 0; j < 4; j++)
            #pragma unroll
            for (int q = 0; q < 4; q++) acc[i][j][q] = 0.f;

    // ---- ldmatrix per-thread address components (inline recompute) ----
    const int raBase = wm * 64 + (lane & 15);                      // + tm*16
    const int cA     = lane >> 4;
    const int rbBase = wn * 32 + (lane & 7) + ((lane >> 4) << 3);  // + g*16
    const int cB     = (lane >> 3) & 1;

    // issue full chunk t into stage s: A 4 sweeps + B 4 sweeps (8 cp.async)
    auto issue = [&](int s, int t) {
        const uint32_t sb = sm0 + s * STAGE_B;
        const size_t ko = (size_t)t * BK;
        #pragma unroll
        for (int i = 0; i < 4; i++) {
            uint32_t roff = (uint32_t)(lr + 32 * i) * 128 + swchunk;
            CP16(sb + roff, srcA + ko + (size_t)(32 * i) * KDIM);
        }
        #pragma unroll
        for (int i = 0; i < 4; i++) {
            uint32_t roff = (uint32_t)(lr + 32 * i) * 128 + swchunk;
            CP16(sb + TILE_A_B + roff, srcB + ko + (size_t)(32 * i) * KDIM);
        }
    };

    // one ks-step of LDSM + MMA (pure block; no copies inside)
    auto step = [&](uint32_t aT, int ks) {
        const uint32_t bT = aT + TILE_A_B;
        uint32_t ah[4][4], bh[2][4];
        #pragma unroll
        for (int tm = 0; tm < 4; tm++) {
            const int r = raBase + tm * 16;
            const uint32_t off = (uint32_t)r * 128 +
                                 (uint32_t)(((2 * ks + cA) ^ (r & 7)) << 4);
            LDSM4(ah[tm][0], ah[tm][1], ah[tm][2], ah[tm][3], aT + off);
        }
        #pragma unroll
        for (int g = 0; g < 2; g++) {
            const int r = rbBase + g * 16;
            const uint32_t off = (uint32_t)r * 128 +
                                 (uint32_t)(((2 * ks + cB) ^ (r & 7)) << 4);
            LDSM4(bh[g][0], bh[g][1], bh[g][2], bh[g][3], bT + off);
        }
        #pragma unroll
        for (int tm = 0; tm < 4; tm++) {
            #pragma unroll
            for (int g = 0; g < 2; g++) {
                #pragma unroll
                for (int h = 0; h < 2; h++) {
                    mma16816(acc[tm][g * 2 + h], ah[tm],
                             bh[g][2 * h], bh[g][2 * h + 1]);
                }
            }
        }
    };

    // distance-2, 3-stage pipeline (R3/R8-proven): iter-t writes (t+2)%3,
    // reads t%3; reads of (t+2)%3 finished at iter t-1, ordered by the
    // top-of-loop barrier.
    issue(0, 0); CP_COMMIT();
    issue(1, 1); CP_COMMIT();

    for (int t = 0; t < NCH; t++) {
        CP_WAIT1();
        __syncthreads();

        const uint32_t aT = sm0 + (t % STAGES) * STAGE_B;

        // first half of compute (post-barrier LDSM burst runs alone)
        step(aT, 0);
        step(aT, 1);

        // single mid-chunk copy point (LSU quiet zone)
        if (t + 2 < NCH) issue((t + 2) % STAGES, t + 2);
        CP_COMMIT();

        step(aT, 2);
        step(aT, 3);
    }

    // ---- epilogue: add bias, store ----
    float2 bv[4];
    #pragma unroll
    for (int j = 0; j < 4; j++) {
        const int n = bn + wn * 32 + j * 8 + 2 * (lane & 3);
        bv[j] = *(const float2*)(bias + n);
    }
    #pragma unroll
    for (int tm = 0; tm < 4; tm++) {
        const int r0 = bm + wm * 64 + tm * 16 + (lane >> 2);
        #pragma unroll
        for (int j = 0; j < 4; j++) {
            const int n = bn + wn * 32 + j * 8 + 2 * (lane & 3);
            float2 o0, o1;
            o0.x = acc[tm][j][0] + bv[j].x;
            o0.y = acc[tm][j][1] + bv[j].y;
            o1.x = acc[tm][j][2] + bv[j].x;
            o1.y = acc[tm][j][3] + bv[j].y;
            *(float2*)(C + (size_t)r0 * NDIM + n)       = o0;
            *(float2*)(C + (size_t)(r0 + 8) * NDIM + n) = o1;
        }
    }
}

// ====================== host launch ======================
extern "C" void kernel_launch(void* const* d_in, const int* in_sizes, int n_in,
                              void* d_out, int out_size) {
    const float* x    = (const float*)d_in[0];   // (4,4096,2048) fp32
    const float* W    = (const float*)d_in[1];   // (2048,2048) fp32
    const float* bias = (const float*)d_in[2];   // (2048,) fp32
    float* out        = (float*)d_out;

    static bool attr_set = false;
    if (!attr_set) {
        cudaFuncSetAttribute(had_gemm_f16, cudaFuncAttributeMaxDynamicSharedMemorySize,
                             SMEM_TOTAL);
        attr_set = true;
    }

    const int conv_blocks = (M_ROWS * KDIM / 4) / (256 * CONV_F4_PER_THREAD);
    preprocess<<<FWHT_BLKS + conv_blocks, 256>>>(W, x);

    dim3 grid(NDIM / BN, M_ROWS / BM);   // bn fastest -> A-stripe L2 reuse
    had_gemm_f16<<<grid, 256, SMEM_TOTAL>>>(bias, out);
}

// round 14
// speedup vs baseline: 1.0593x; 1.0183x over previous
#include <cuda_runtime.h>
#include <cuda_fp16.h>
#include <cstdint>

// out[m,o] = sum_d FWHT(x)[m,d] * W[o,d] / sqrt(D) + b[o]
// Hadamard symmetric => FWHT(x) @ W^T == x @ (FWHT_rows(W))^T.
// fp16 single-pass HMMA GEMM w/ fp32 acc.
// R14: 8 warps x 64x64 warp tiles (128B LDSM/MMA -> crossbar off critical
// path) + explicit fragment double-buffering across k16-steps (covers the
// LDSM->MMA latency that sank R7's identical shape). BK=128 / 2-stage / one
// mid-chunk copy point, all R11-proven.

#define D_DIM 2048
#define M_ROWS 16384
#define KDIM 2048
#define NDIM 2048

#define BM 256
#define BN 128
#define BKH 64                       // layout sub-chunk (one SW-atom k-half)
#define NCH (KDIM / (2 * BKH))       // 16 double-chunks
#define TILE_A_B (BM * 128)          // 32 KB per k-half
#define TILE_B_B (BN * 128)          // 16 KB per k-half
#define HALF_B (TILE_A_B + TILE_B_B) // 48 KB
#define STAGE_B (2 * HALF_B)         // 96 KB (BK=128)
#define SMEM_TOTAL (2 * STAGE_B)     // 192 KB, 1 CTA/SM

// ---- device-global scratch ----
__device__ __half g_W_h[(size_t)NDIM * KDIM];     // 8 MB
__device__ __half g_x_h[(size_t)M_ROWS * KDIM];   // 64 MB

// ====================== PTX helpers ======================
__device__ __forceinline__ uint32_t smem_u32(const void* p) {
    uint32_t a;
    asm("{ .reg .u64 t; cvta.to.shared.u64 t, %1; cvt.u32.u64 %0, t; }" : "=r"(a) : "l"(p));
    return a;
}
#define CP16(dst, src) \
    asm volatile("cp.async.cg.shared.global [%0], [%1], 16;" :: "r"(dst), "l"(src))
#define CP_COMMIT() asm volatile("cp.async.commit_group;" ::: "memory")
#define CP_WAIT0()  asm volatile("cp.async.wait_group 0;" ::: "memory")

#define LDSM4(r0, r1, r2, r3, addr) \
    asm volatile("ldmatrix.sync.aligned.m8n8.x4.shared.b16 {%0,%1,%2,%3}, [%4];" \
                 : "=r"(r0), "=r"(r1), "=r"(r2), "=r"(r3) : "r"(addr))

__device__ __forceinline__ void mma16816(float* c, const uint32_t* a,
                                         uint32_t b0, uint32_t b1) {
    asm volatile(
        "mma.sync.aligned.m16n8k16.row.col.f32.f16.f16.f32 "
        "{%0,%1,%2,%3}, {%4,%5,%6,%7}, {%8,%9}, {%0,%1,%2,%3};"
        : "+f"(c[0]), "+f"(c[1]), "+f"(c[2]), "+f"(c[3])
        : "r"(a[0]), "r"(a[1]), "r"(a[2]), "r"(a[3]), "r"(b0), "r"(b1));
}

// ============ Kernel 1 (merged preprocessing) ============
#define FWHT_BLKS (D_DIM / 2)
#define CONV_F4_PER_THREAD 4
__global__ __launch_bounds__(256) void preprocess(const float* __restrict__ W,
                                                  const float* __restrict__ x) {
    __shared__ float s[2 * D_DIM];
    const int tid = threadIdx.x;
    if (blockIdx.x < FWHT_BLKS) {
        const float* rows = W + (size_t)blockIdx.x * 2 * D_DIM;
        for (int i = tid; i < 2 * D_DIM; i += 256) s[i] = rows[i];
        __syncthreads();
        #pragma unroll
        for (int lg = 0; lg < 11; lg++) {
            int h = 1 << lg;
            #pragma unroll
            for (int rr = 0; rr < 2; rr++) {
                float* sr = s + rr * D_DIM;
                #pragma unroll
                for (int q = 0; q < (D_DIM / 2) / 256; q++) {
                    int p = tid + q * 256;
                    int i = ((p >> lg) << (lg + 1)) | (p & (h - 1));
                    float a = sr[i], c = sr[i + h];
                    sr[i] = a + c;
                    sr[i + h] = a - c;
                }
            }
            __syncthreads();
        }
        const float scale = 0.02209708691207961f;  // 1/sqrt(2048)
        size_t base = (size_t)blockIdx.x * 2 * D_DIM;
        for (int i = tid; i < 2 * D_DIM; i += 256)
            g_W_h[base + i] = __float2half_rn(s[i] * scale);
    } else {
        size_t b = (size_t)(blockIdx.x - FWHT_BLKS) * (256 * CONV_F4_PER_THREAD) + tid;
        float4 v[CONV_F4_PER_THREAD];
        #pragma unroll
        for (int u = 0; u < CONV_F4_PER_THREAD; u++)
            v[u] = ((const float4*)x)[b + (size_t)u * 256];
        #pragma unroll
        for (int u = 0; u < CONV_F4_PER_THREAD; u++) {
            size_t i = b + (size_t)u * 256;
            ((__half2*)g_x_h)[2 * i]     = __floats2half2_rn(v[u].x, v[u].y);
            ((__half2*)g_x_h)[2 * i + 1] = __floats2half2_rn(v[u].z, v[u].w);
        }
    }
}

// ====================== Kernel 2: fp16 HMMA GEMM + bias ======================
// 8 warps: wm = wid&3 (4 x 64 rows = 256), wn = wid>>2 (2 x 64 cols = 128).
// Warp tile 64x64: per k16-step A 4 LDSM4 + B 4 LDSM4, 32 MMAs (128B/MMA).
// Fragments double-buffered: LDSM for ks+1 issued before MMAs of ks.

__global__ __launch_bounds__(256, 1)
void had_gemm_f16(const float* __restrict__ bias, float* __restrict__ C) {
    extern __shared__ __align__(1024) char smem[];
    const uint32_t sm0 = smem_u32(smem);

    const int tid  = threadIdx.x;
    const int lane = tid & 31;
    const int wid  = tid >> 5;
    const int wm   = wid & 3;
    const int wn   = wid >> 2;

    const int bm = blockIdx.y * BM;
    const int bn = blockIdx.x * BN;

    // ---- cp.async loader mapping: row lr (+32*i), 16B chunk lc ----
    const int lr = tid >> 3;      // 0..31
    const int lc = tid & 7;
    const uint32_t swchunk = (uint32_t)((lc ^ (lr & 7)) << 4);

    const __half* srcA = g_x_h + (size_t)(bm + lr) * KDIM + lc * 8;
    const __half* srcB = g_W_h + (size_t)(bn + lr) * KDIM + lc * 8;

    float acc[4][8][4];
    #pragma unroll
    for (int i = 0; i < 4; i++)
        #pragma unroll
        for (int j = 0; j < 8; j++)
            #pragma unroll
            for (int q = 0; q < 4; q++) acc[i][j][q] = 0.f;

    // ---- ldmatrix per-thread address components (inline recompute) ----
    const int raBase = wm * 64 + (lane & 15);                      // + tm*16
    const int cA     = lane >> 4;
    const int rbBase = wn * 64 + (lane & 7) + ((lane >> 4) << 3);  // + g*16
    const int cB     = (lane >> 3) & 1;

    // double-buffered fragments
    uint32_t ah[2][4][4], bh[2][4][4];

    // load all 8 LDSM4 fragments of k16-step ks from half base aT into buf
    auto load_frags = [&](uint32_t aT, int ks, int buf) {
        const uint32_t bT = aT + TILE_A_B;
        #pragma unroll
        for (int tm = 0; tm < 4; tm++) {
            const int r = raBase + tm * 16;
            const uint32_t off = (uint32_t)r * 128 +
                                 (uint32_t)(((2 * ks + cA) ^ (r & 7)) << 4);
            LDSM4(ah[buf][tm][0], ah[buf][tm][1], ah[buf][tm][2], ah[buf][tm][3],
                  aT + off);
        }
        #pragma unroll
        for (int g = 0; g < 4; g++) {
            const int r = rbBase + g * 16;
            const uint32_t off = (uint32_t)r * 128 +
                                 (uint32_t)(((2 * ks + cB) ^ (r & 7)) << 4);
            LDSM4(bh[buf][g][0], bh[buf][g][1], bh[buf][g][2], bh[buf][g][3],
                  bT + off);
        }
    };

    // pure MMA block on buffer buf
    auto mma_all = [&](int buf) {
        #pragma unroll
        for (int tm = 0; tm < 4; tm++) {
            #pragma unroll
            for (int g = 0; g < 4; g++) {
                #pragma unroll
                for (int h = 0; h < 2; h++) {
                    mma16816(acc[tm][g * 2 + h], ah[buf][tm],
                             bh[buf][g][2 * h], bh[buf][g][2 * h + 1]);
                }
            }
        }
    };

    // issue ONE k-half (BKH=64) of chunk t into stage s, half h01
    auto issue_half = [&](int s, int t, int h01) {
        const uint32_t hb = sm0 + s * STAGE_B + h01 * HALF_B;
        const size_t ko = (size_t)t * (2 * BKH) + (size_t)h01 * BKH;
        #pragma unroll
        for (int i = 0; i < 8; i++) {             // A: 256 rows / 32
            uint32_t roff = (uint32_t)(lr + 32 * i) * 128 + swchunk;
            CP16(hb + roff, srcA + ko + (size_t)(32 * i) * KDIM);
        }
        #pragma unroll
        for (int i = 0; i < 4; i++) {             // B: 128 rows / 32
            uint32_t roff = (uint32_t)(lr + 32 * i) * 128 + swchunk;
            CP16(hb + TILE_A_B + roff, srcB + ko + (size_t)(32 * i) * KDIM);
        }
    };

    // 2-stage pipeline: write stage (t+1)&1 != read stage t&1; top-of-loop
    // barrier orders prior reads of the write-stage before its overwrite.
    issue_half(0, 0, 0); issue_half(0, 0, 1); CP_COMMIT();

    for (int t = 0; t < NCH; t++) {
        CP_WAIT0();            // chunk t fully in smem
        __syncthreads();

        const uint32_t h0 = sm0 + (t & 1) * STAGE_B;
        const uint32_t h1 = h0 + HALF_B;

        // ---- half 0: frag-pipelined ----
        load_frags(h0, 0, 0);
        load_frags(h0, 1, 1); mma_all(0);
        load_frags(h0, 2, 0); mma_all(1);
        load_frags(h0, 3, 1); mma_all(0);
        load_frags(h1, 0, 0); mma_all(1);      // cross-half prefetch

        // single mid-chunk copy point (LSU quiet zone)
        if (t + 1 < NCH) {
            issue_half((t + 1) & 1, t + 1, 0);
            issue_half((t + 1) & 1, t + 1, 1);
        }
        CP_COMMIT();

        // ---- half 1: frag-pipelined ----
        load_frags(h1, 1, 1); mma_all(0);
        load_frags(h1, 2, 0); mma_all(1);
        load_frags(h1, 3, 1); mma_all(0);
        mma_all(1);
    }

    // ---- epilogue: add bias, store ----
    float2 bv[8];
    #pragma unroll
    for (int j = 0; j < 8; j++) {
        const int n = bn + wn * 64 + j * 8 + 2 * (lane & 3);
        bv[j] = *(const float2*)(bias + n);
    }
    #pragma unroll
    for (int tm = 0; tm < 4; tm++) {
        const int r0 = bm + wm * 64 + tm * 16 + (lane >> 2);
        #pragma unroll
        for (int j = 0; j < 8; j++) {
            const int n = bn + wn * 64 + j * 8 + 2 * (lane & 3);
            float2 o0, o1;
            o0.x = acc[tm][j][0] + bv[j].x;
            o0.y = acc[tm][j][1] + bv[j].y;
            o1.x = acc[tm][j][2] + bv[j].x;
            o1.y = acc[tm][j][3] + bv[j].y;
            *(float2*)(C + (size_t)r0 * NDIM + n)       = o0;
            *(float2*)(C + (size_t)(r0 + 8) * NDIM + n) = o1;
        }
    }
}

// ====================== host launch ======================
extern "C" void kernel_launch(void* const* d_in, const int* in_sizes, int n_in,
                              void* d_out, int out_size) {
    const float* x    = (const float*)d_in[0];   // (4,4096,2048) fp32
    const float* W    = (const float*)d_in[1];   // (2048,2048) fp32
    const float* bias = (const float*)d_in[2];   // (2048,) fp32
    float* out        = (float*)d_out;

    static bool attr_set = false;
    if (!attr_set) {
        cudaFuncSetAttribute(had_gemm_f16, cudaFuncAttributeMaxDynamicSharedMemorySize,
                             SMEM_TOTAL);
        attr_set = true;
    }

    const int conv_blocks = (M_ROWS * KDIM / 4) / (256 * CONV_F4_PER_THREAD);
    preprocess<<<FWHT_BLKS + conv_blocks, 256>>>(W, x);

    dim3 grid(NDIM / BN, M_ROWS / BM);   // bn fastest -> A-stripe L2 reuse
    had_gemm_f16<<<grid, 256, SMEM_TOTAL>>>(bias, out);
}